// round 13
// baseline (speedup 1.0000x reference)
#include <cuda_runtime.h>
#include <cuda_bf16.h>
#include <cstdint>

#define IN_F   512
#define OUT_F  512
#define NBAT   8192
#define NFEAT  12                      // 1 raw x + 11 spline bases
#define KB     (IN_F * NFEAT)          // 6144 (K of one hi/lo block)
#define ROWB   (KB * 2)                // 12288 B global row stride
#define NCH    (3 * KB / 64)           // 288 chunks (3 products x 96 segs)
#define STG    4
#define M_TILE 128
#define N_TILE 256
#define A_BYTES (M_TILE * 128)                    // 16 KB
#define B_BYTES (N_TILE * 128)                    // 32 KB
#define STAGE_BYTES (A_BYTES + B_BYTES)           // 49152
#define SMEM_TOTAL  (STG * STAGE_BYTES)           // 196608

// ---------------- scratch (device globals: allocation-free) ----------------
__device__ __nv_bfloat16 g_Ah[(size_t)NBAT * KB];     // 100.7 MB
__device__ __nv_bfloat16 g_Al[(size_t)NBAT * KB];     // 100.7 MB
__device__ __nv_bfloat16 g_Bh[(size_t)OUT_F * KB];    // 6.3 MB
__device__ __nv_bfloat16 g_Bl[(size_t)OUT_F * KB];    // 6.3 MB

// ---------------- PTX helpers (base-sm_80+ only) ---------------------------
__device__ __forceinline__ uint32_t smem_u32(const void* p) {
    uint32_t a;
    asm("{ .reg .u64 t; cvta.to.shared.u64 t, %1; cvt.u32.u64 %0, t; }" : "=r"(a) : "l"(p));
    return a;
}
__device__ __forceinline__ void cp16(uint32_t dst, const void* src) {
    asm volatile("cp.async.cg.shared.global [%0], [%1], 16;" :: "r"(dst), "l"(src));
}
#define CP_COMMIT() asm volatile("cp.async.commit_group;" ::: "memory")
#define CP_WAIT_2() asm volatile("cp.async.wait_group 2;" ::: "memory")

__device__ __forceinline__ void ldsm4(uint32_t& r0, uint32_t& r1, uint32_t& r2,
                                      uint32_t& r3, uint32_t addr) {
    asm volatile("ldmatrix.sync.aligned.m8n8.x4.shared.b16 {%0,%1,%2,%3}, [%4];"
                 : "=r"(r0), "=r"(r1), "=r"(r2), "=r"(r3) : "r"(addr));
}
__device__ __forceinline__ void mma16816(float& d0, float& d1, float& d2, float& d3,
                                         uint32_t a0, uint32_t a1, uint32_t a2, uint32_t a3,
                                         uint32_t b0, uint32_t b1) {
    asm volatile(
        "mma.sync.aligned.m16n8k16.row.col.f32.bf16.bf16.f32 "
        "{%0,%1,%2,%3}, {%4,%5,%6,%7}, {%8,%9}, {%0,%1,%2,%3};"
        : "+f"(d0), "+f"(d1), "+f"(d2), "+f"(d3)
        : "r"(a0), "r"(a1), "r"(a2), "r"(a3), "r"(b0), "r"(b1));
}
// 128-byte smem rows, XOR-(r&7) swizzle; k16 step s = XOR (s<<5) on the address.
__device__ __forceinline__ uint32_t swz(int r, int c) {
    return (uint32_t)(r * 128 + ((c ^ (r & 7)) << 4));
}

// ---------------- basis (identical math to all passing kernels) ------------
__device__ __forceinline__ void aug_features(float xr, float* bb) {
    float xc = fminf(fmaxf(xr, -2.0f), 2.0f);
    float g[15];
#pragma unroll
    for (int m = 0; m < 15; ++m) g[m] = fmaf((float)m, 2.0f / 14.0f, -1.0f);
    float b[14];
#pragma unroll
    for (int m = 0; m < 14; ++m) b[m] = (xc >= g[m] && xc < g[m + 1]) ? 1.0f : 0.0f;
#pragma unroll
    for (int k = 1; k <= 3; ++k) {
        float inv = 7.0f / (float)k;
#pragma unroll
        for (int m = 0; m < 14 - k; ++m)
            b[m] = (xc - g[m]) * inv * b[m] + (g[m + k + 1] - xc) * inv * b[m + 1];
    }
    bb[0] = xr;
#pragma unroll
    for (int j = 0; j < 11; ++j) bb[1 + j] = b[j];
}

// ---------------- prep_B: weights -> B_hi / B_lo ---------------------------
__global__ __launch_bounds__(256) void prep_B(const float* __restrict__ bw,
                                              const float* __restrict__ sw) {
    int idx = blockIdx.x * 256 + threadIdx.x;        // (o, i)
    int o = idx >> 9, i = idx & 511;
    float v[NFEAT];
    v[0] = bw[(size_t)o * IN_F + i];
#pragma unroll
    for (int j = 0; j < 11; ++j) v[1 + j] = sw[((size_t)o * IN_F + i) * 11 + j];
    unsigned short sh[NFEAT], sl[NFEAT];
#pragma unroll
    for (int c = 0; c < NFEAT; ++c) {
        __nv_bfloat16 h = __float2bfloat16(v[c]);
        __nv_bfloat16 l = __float2bfloat16(v[c] - __bfloat162float(h));
        sh[c] = __bfloat16_as_ushort(h);  sl[c] = __bfloat16_as_ushort(l);
    }
    size_t off = (size_t)o * KB + (size_t)i * NFEAT;
    unsigned long long* dh = (unsigned long long*)(g_Bh + off);
    unsigned long long* dl = (unsigned long long*)(g_Bl + off);
#pragma unroll
    for (int j = 0; j < 3; ++j) {
        dh[j] = (unsigned long long)sh[4 * j] |
                ((unsigned long long)sh[4 * j + 1] << 16) |
                ((unsigned long long)sh[4 * j + 2] << 32) |
                ((unsigned long long)sh[4 * j + 3] << 48);
        dl[j] = (unsigned long long)sl[4 * j] |
                ((unsigned long long)sl[4 * j + 1] << 16) |
                ((unsigned long long)sl[4 * j + 2] << 32) |
                ((unsigned long long)sl[4 * j + 3] << 48);
    }
}

// ---------------- fused GEMM: 512 threads, 16 warps ------------------------
// CTA 128x256, warps 4(M) x 4(N), warp tile 32x64.
// Prologue (validated Round 8): build this CTA's A_hi/A_lo slice, then
// __threadfence so cp.async.cg (L2 path) sees the data.
// Mainloop (validated Rounds 10/11): single chunk per barrier, STG=4,
// CP_WAIT_2, lookahead 3.  Chunk u: product u%3 in {(Ah,Bh),(Ah,Bl),(Al,Bh)},
// k-offset (u/3)*64.
__global__ __launch_bounds__(512, 1) void kan_gemm(const float* __restrict__ x,
                                                   float* __restrict__ out) {
    extern __shared__ __align__(1024) unsigned char smem[];
    const uint32_t sbase = smem_u32(smem);
    const int tid  = threadIdx.x;
    const int lane = tid & 31;
    const int wid  = tid >> 5;
    const int warpM = wid & 3;          // 0..3 -> 32-row slice
    const int warpN = wid >> 2;         // 0..3 -> 64-col slice
    const int mBase = blockIdx.y * M_TILE;
    const int nBase = blockIdx.x * N_TILE;

    // ---- prologue: split-A slice for this CTA's 128 rows ------------------
    {
        const float* xrow = x + (size_t)mBase * IN_F;
#pragma unroll 1
        for (int j = 0; j < (M_TILE * IN_F) / 512; ++j) {   // 128 iters
            int idx = j * 512 + tid;
            int m = idx >> 9, i = idx & 511;
            float bb[NFEAT];
            aug_features(xrow[idx], bb);
            unsigned short sh[NFEAT], sl[NFEAT];
#pragma unroll
            for (int c = 0; c < NFEAT; ++c) {
                __nv_bfloat16 h = __float2bfloat16(bb[c]);
                __nv_bfloat16 l = __float2bfloat16(bb[c] - __bfloat162float(h));
                sh[c] = __bfloat16_as_ushort(h);  sl[c] = __bfloat16_as_ushort(l);
            }
            size_t off = (size_t)(mBase + m) * KB + (size_t)i * NFEAT;
            unsigned long long* dh = (unsigned long long*)(g_Ah + off);
            unsigned long long* dl = (unsigned long long*)(g_Al + off);
#pragma unroll
            for (int q = 0; q < 3; ++q) {
                dh[q] = (unsigned long long)sh[4 * q] |
                        ((unsigned long long)sh[4 * q + 1] << 16) |
                        ((unsigned long long)sh[4 * q + 2] << 32) |
                        ((unsigned long long)sh[4 * q + 3] << 48);
                dl[q] = (unsigned long long)sl[4 * q] |
                        ((unsigned long long)sl[4 * q + 1] << 16) |
                        ((unsigned long long)sl[4 * q + 2] << 32) |
                        ((unsigned long long)sl[4 * q + 3] << 48);
            }
        }
        __threadfence();          // writes L2-visible before cp.async reads
        __syncthreads();
    }

    const char* Ah = (const char*)(g_Ah + (size_t)mBase * KB);
    const char* Al = (const char*)(g_Al + (size_t)mBase * KB);
    const char* Bh = (const char*)(g_Bh + (size_t)nBase * KB);
    const char* Bl = (const char*)(g_Bl + (size_t)nBase * KB);

    // ---- cp.async coords: granule (r, c) = (tid>>3, tid&7) ----------------
    const int gr = tid >> 3, gc = tid & 7;            // gr 0..63
    uint32_t aDst[2], bDst[4];
#pragma unroll
    for (int j = 0; j < 2; ++j) aDst[j] = swz(gr + 64 * j, gc);
#pragma unroll
    for (int j = 0; j < 4; ++j) bDst[j] = (uint32_t)A_BYTES + swz(gr + 64 * j, gc);
    const size_t aRow0 = (size_t)gr * ROWB + gc * 16;
    const size_t aRow1 = (size_t)(gr + 64) * ROWB + gc * 16;
    size_t bRow[4];
#pragma unroll
    for (int j = 0; j < 4; ++j) bRow[j] = (size_t)(gr + 64 * j) * ROWB + gc * 16;

    auto load_stage = [&](int u) {
        const uint32_t st = sbase + (uint32_t)(u & (STG - 1)) * STAGE_BYTES;
        const int sel = u % 3;
        const size_t ch = (size_t)(u / 3) * 128;
        const char* aB = (sel < 2 ? Ah : Al) + ch;
        const char* bB = (sel == 1 ? Bl : Bh) + ch;
        cp16(st + aDst[0], aB + aRow0);
        cp16(st + aDst[1], aB + aRow1);
#pragma unroll
        for (int j = 0; j < 4; ++j) cp16(st + bDst[j], bB + bRow[j]);
    };

    // ---- ldmatrix lane addressing (k-step advance = XOR (s<<5)) -----------
    const int lr = lane & 15;
    const int lc = lane >> 4;
    uint32_t aOff[2], bOff[4];
#pragma unroll
    for (int t = 0; t < 2; ++t)
        aOff[t] = swz(warpM * 32 + t * 16 + lr, lc);
#pragma unroll
    for (int t = 0; t < 4; ++t)
        bOff[t] = (uint32_t)A_BYTES + swz(warpN * 64 + t * 16 + lr, lc);

    float acc[2][8][4];
#pragma unroll
    for (int mt = 0; mt < 2; ++mt)
#pragma unroll
        for (int nt = 0; nt < 8; ++nt)
#pragma unroll
            for (int q = 0; q < 4; ++q) acc[mt][nt][q] = 0.0f;

    for (int i = 0; i < STG - 1; ++i) { load_stage(i); CP_COMMIT(); }

#pragma unroll 1
    for (int i = 0; i < NCH; ++i) {
        CP_WAIT_2();                 // chunk i resident (2 newer groups pending)
        __syncthreads();             // all warps done with the slot being refilled
        const int nc = i + STG - 1;
        if (nc < NCH) load_stage(nc);
        CP_COMMIT();                 // one group per iter (may be empty)

        const uint32_t st = sbase + (uint32_t)(i & (STG - 1)) * STAGE_BYTES;
#pragma unroll
        for (int s = 0; s < 4; ++s) {
            const uint32_t kx = (uint32_t)s << 5;
            uint32_t a[2][4], b[4][4];
#pragma unroll
            for (int t = 0; t < 2; ++t)
                ldsm4(a[t][0], a[t][1], a[t][2], a[t][3], st + (aOff[t] ^ kx));
#pragma unroll
            for (int t = 0; t < 4; ++t)
                ldsm4(b[t][0], b[t][1], b[t][2], b[t][3], st + (bOff[t] ^ kx));
#pragma unroll
            for (int mt = 0; mt < 2; ++mt)
#pragma unroll
                for (int t = 0; t < 4; ++t) {
                    mma16816(acc[mt][2*t][0], acc[mt][2*t][1], acc[mt][2*t][2], acc[mt][2*t][3],
                             a[mt][0], a[mt][1], a[mt][2], a[mt][3], b[t][0], b[t][2]);
                    mma16816(acc[mt][2*t+1][0], acc[mt][2*t+1][1], acc[mt][2*t+1][2], acc[mt][2*t+1][3],
                             a[mt][0], a[mt][1], a[mt][2], a[mt][3], b[t][1], b[t][3]);
                }
        }
    }

    // ---- epilogue: direct STG of register accumulators --------------------
    const int mRow = mBase + warpM * 32 + (lane >> 2);
    const int nCol = nBase + warpN * 64 + (lane & 3) * 2;
#pragma unroll
    for (int mt = 0; mt < 2; ++mt) {
        float* r0 = out + (size_t)(mRow + mt * 16)     * OUT_F + nCol;
        float* r1 = out + (size_t)(mRow + mt * 16 + 8) * OUT_F + nCol;
#pragma unroll
        for (int nt = 0; nt < 8; ++nt) {
            *(float2*)(r0 + nt * 8) = make_float2(acc[mt][nt][0], acc[mt][nt][1]);
            *(float2*)(r1 + nt * 8) = make_float2(acc[mt][nt][2], acc[mt][nt][3]);
        }
    }
}

// ---------------- launch ---------------------------------------------------
extern "C" void kernel_launch(void* const* d_in, const int* in_sizes, int n_in,
                              void* d_out, int out_size) {
    const float* x  = (const float*)d_in[0];
    const float* bw = (const float*)d_in[1];
    const float* sw = (const float*)d_in[2];
    float* out = (float*)d_out;

    cudaFuncSetAttribute(kan_gemm, cudaFuncAttributeMaxDynamicSharedMemorySize,
                         SMEM_TOTAL);

    prep_B<<<(OUT_F * IN_F) / 256, 256>>>(bw, sw);
    kan_gemm<<<dim3(OUT_F / N_TILE, NBAT / M_TILE), 512, SMEM_TOTAL>>>(x, out);
}

// round 16
// speedup vs baseline: 1.2343x; 1.2343x over previous
#include <cuda_runtime.h>
#include <cuda_bf16.h>
#include <cstdint>

#define IN_F   512
#define OUT_F  512
#define NBAT   8192
#define NFEAT  12                      // 1 raw x + 11 spline bases
#define KB     (IN_F * NFEAT)          // 6144 (K of one hi/lo block)
#define ROWB   (KB * 2)                // 12288 B global row stride
#define NCH    (3 * KB / 64)           // 288 chunks (3 products x 96 segs)
#define NGRP   (NCH / 2)               // 144 chunk-pairs
#define STG    4
#define M_TILE 128
#define N_TILE 256
#define A_BYTES (M_TILE * 128)                    // 16 KB
#define B_BYTES (N_TILE * 128)                    // 32 KB
#define STAGE_BYTES (A_BYTES + B_BYTES)           // 49152
#define SMEM_TOTAL  (STG * STAGE_BYTES)           // 196608

// ---------------- scratch (device globals: allocation-free) ----------------
__device__ __nv_bfloat16 g_Ah[(size_t)NBAT * KB];     // 100.7 MB
__device__ __nv_bfloat16 g_Al[(size_t)NBAT * KB];     // 100.7 MB
__device__ __nv_bfloat16 g_Bh[(size_t)OUT_F * KB];    // 6.3 MB
__device__ __nv_bfloat16 g_Bl[(size_t)OUT_F * KB];    // 6.3 MB

// ---------------- PTX helpers (base-sm_80+ only) ---------------------------
__device__ __forceinline__ uint32_t smem_u32(const void* p) {
    uint32_t a;
    asm("{ .reg .u64 t; cvta.to.shared.u64 t, %1; cvt.u32.u64 %0, t; }" : "=r"(a) : "l"(p));
    return a;
}
__device__ __forceinline__ void cp16(uint32_t dst, const void* src) {
    asm volatile("cp.async.cg.shared.global [%0], [%1], 16;" :: "r"(dst), "l"(src));
}
#define CP_COMMIT() asm volatile("cp.async.commit_group;" ::: "memory")
#define CP_WAIT_0() asm volatile("cp.async.wait_group 0;" ::: "memory")

__device__ __forceinline__ void ldsm4(uint32_t& r0, uint32_t& r1, uint32_t& r2,
                                      uint32_t& r3, uint32_t addr) {
    asm volatile("ldmatrix.sync.aligned.m8n8.x4.shared.b16 {%0,%1,%2,%3}, [%4];"
                 : "=r"(r0), "=r"(r1), "=r"(r2), "=r"(r3) : "r"(addr));
}
__device__ __forceinline__ void mma16816(float& d0, float& d1, float& d2, float& d3,
                                         uint32_t a0, uint32_t a1, uint32_t a2, uint32_t a3,
                                         uint32_t b0, uint32_t b1) {
    asm volatile(
        "mma.sync.aligned.m16n8k16.row.col.f32.bf16.bf16.f32 "
        "{%0,%1,%2,%3}, {%4,%5,%6,%7}, {%8,%9}, {%0,%1,%2,%3};"
        : "+f"(d0), "+f"(d1), "+f"(d2), "+f"(d3)
        : "r"(a0), "r"(a1), "r"(a2), "r"(a3), "r"(b0), "r"(b1));
}
// 128-byte smem rows, XOR-(r&7) swizzle; k16 step s = XOR (s<<5) on the address.
__device__ __forceinline__ uint32_t swz(int r, int c) {
    return (uint32_t)(r * 128 + ((c ^ (r & 7)) << 4));
}

// ---------------- basis (identical math to all passing kernels) ------------
__device__ __forceinline__ void aug_features(float xr, float* bb) {
    float xc = fminf(fmaxf(xr, -2.0f), 2.0f);
    float g[15];
#pragma unroll
    for (int m = 0; m < 15; ++m) g[m] = fmaf((float)m, 2.0f / 14.0f, -1.0f);
    float b[14];
#pragma unroll
    for (int m = 0; m < 14; ++m) b[m] = (xc >= g[m] && xc < g[m + 1]) ? 1.0f : 0.0f;
#pragma unroll
    for (int k = 1; k <= 3; ++k) {
        float inv = 7.0f / (float)k;
#pragma unroll
        for (int m = 0; m < 14 - k; ++m)
            b[m] = (xc - g[m]) * inv * b[m] + (g[m + k + 1] - xc) * inv * b[m + 1];
    }
    bb[0] = xr;
#pragma unroll
    for (int j = 0; j < 11; ++j) bb[1 + j] = b[j];
}

// ---------------- P1: activations -> A_hi / A_lo (2 features/thread) -------
__global__ __launch_bounds__(256) void prep_A(const float* __restrict__ x) {
    int p  = blockIdx.x * 256 + threadIdx.x;
    int m  = p >> 8;
    int ip = (p & 255) * 2;                          // even feature index

    float2 xv = *(const float2*)&x[(size_t)m * IN_F + ip];
    uint32_t wh[12], wl[12];
#pragma unroll
    for (int f = 0; f < 2; ++f) {
        float bb[NFEAT];
        aug_features(f ? xv.y : xv.x, bb);
        unsigned short sh[NFEAT], sl[NFEAT];
#pragma unroll
        for (int c = 0; c < NFEAT; ++c) {
            __nv_bfloat16 h = __float2bfloat16(bb[c]);
            __nv_bfloat16 l = __float2bfloat16(bb[c] - __bfloat162float(h));
            sh[c] = __bfloat16_as_ushort(h);  sl[c] = __bfloat16_as_ushort(l);
        }
#pragma unroll
        for (int k = 0; k < 6; ++k) {
            wh[f * 6 + k] = (uint32_t)sh[2 * k] | ((uint32_t)sh[2 * k + 1] << 16);
            wl[f * 6 + k] = (uint32_t)sl[2 * k] | ((uint32_t)sl[2 * k + 1] << 16);
        }
    }
    size_t off = (size_t)m * KB + (size_t)ip * NFEAT;
    uint4* dh = (uint4*)(g_Ah + off);
    uint4* dl = (uint4*)(g_Al + off);
#pragma unroll
    for (int j = 0; j < 3; ++j) {
        dh[j] = make_uint4(wh[4 * j], wh[4 * j + 1], wh[4 * j + 2], wh[4 * j + 3]);
        dl[j] = make_uint4(wl[4 * j], wl[4 * j + 1], wl[4 * j + 2], wl[4 * j + 3]);
    }
}

// ---------------- P2: weights -> B_hi / B_lo -------------------------------
__global__ __launch_bounds__(256) void prep_B(const float* __restrict__ bw,
                                              const float* __restrict__ sw) {
    int idx = blockIdx.x * 256 + threadIdx.x;        // (o, i)
    int o = idx >> 9, i = idx & 511;
    float v[NFEAT];
    v[0] = bw[(size_t)o * IN_F + i];
#pragma unroll
    for (int j = 0; j < 11; ++j) v[1 + j] = sw[((size_t)o * IN_F + i) * 11 + j];
    unsigned short sh[NFEAT], sl[NFEAT];
#pragma unroll
    for (int c = 0; c < NFEAT; ++c) {
        __nv_bfloat16 h = __float2bfloat16(v[c]);
        __nv_bfloat16 l = __float2bfloat16(v[c] - __bfloat162float(h));
        sh[c] = __bfloat16_as_ushort(h);  sl[c] = __bfloat16_as_ushort(l);
    }
    size_t off = (size_t)o * KB + (size_t)i * NFEAT;
    unsigned long long* dh = (unsigned long long*)(g_Bh + off);
    unsigned long long* dl = (unsigned long long*)(g_Bl + off);
#pragma unroll
    for (int j = 0; j < 3; ++j) {
        dh[j] = (unsigned long long)sh[4 * j] |
                ((unsigned long long)sh[4 * j + 1] << 16) |
                ((unsigned long long)sh[4 * j + 2] << 32) |
                ((unsigned long long)sh[4 * j + 3] << 48);
        dl[j] = (unsigned long long)sl[4 * j] |
                ((unsigned long long)sl[4 * j + 1] << 16) |
                ((unsigned long long)sl[4 * j + 2] << 32) |
                ((unsigned long long)sl[4 * j + 3] << 48);
    }
}

// ---------------- G: mma.sync bf16 GEMM, 512 threads, 16 warps -------------
// CTA 128x256, warps 4(M) x 4(N), warp tile 32x64.
// 144 chunk-PAIRS; pairs alternate slot-sets {0,1}/{2,3}.  Per pair g:
//   CP_WAIT_0        -> pair g resident (only group in flight)
//   __syncthreads    -> pair g visible to all warps AND pair g-1 compute done
//   load pair g+1    -> into pair g-1's slots (safe by the sync)
//   compute pair g   -> overlaps pair g+1's flight
// Chunk u: product u%3 in {(Ah,Bh),(Ah,Bl),(Al,Bh)}, k-offset (u/3)*64.
__global__ __launch_bounds__(512, 1) void kan_gemm(float* __restrict__ out) {
    extern __shared__ __align__(1024) unsigned char smem[];
    const uint32_t sbase = smem_u32(smem);
    const int tid  = threadIdx.x;
    const int lane = tid & 31;
    const int wid  = tid >> 5;
    const int warpM = wid & 3;          // 0..3 -> 32-row slice
    const int warpN = wid >> 2;         // 0..3 -> 64-col slice
    const int mBase = blockIdx.y * M_TILE;
    const int nBase = blockIdx.x * N_TILE;

    const char* Ah = (const char*)(g_Ah + (size_t)mBase * KB);
    const char* Al = (const char*)(g_Al + (size_t)mBase * KB);
    const char* Bh = (const char*)(g_Bh + (size_t)nBase * KB);
    const char* Bl = (const char*)(g_Bl + (size_t)nBase * KB);

    // ---- cp.async coords: granule (r, c) = (tid>>3, tid&7) ----------------
    const int gr = tid >> 3, gc = tid & 7;            // gr 0..63
    uint32_t aDst[2], bDst[4];
#pragma unroll
    for (int j = 0; j < 2; ++j) aDst[j] = swz(gr + 64 * j, gc);
#pragma unroll
    for (int j = 0; j < 4; ++j) bDst[j] = (uint32_t)A_BYTES + swz(gr + 64 * j, gc);
    const size_t aRow0 = (size_t)gr * ROWB + gc * 16;
    const size_t aRow1 = (size_t)(gr + 64) * ROWB + gc * 16;
    size_t bRow[4];
#pragma unroll
    for (int j = 0; j < 4; ++j) bRow[j] = (size_t)(gr + 64 * j) * ROWB + gc * 16;

    auto load_stage = [&](int u) {
        const uint32_t st = sbase + (uint32_t)(u & (STG - 1)) * STAGE_BYTES;
        const int sel = u % 3;
        const size_t ch = (size_t)(u / 3) * 128;
        const char* aB = (sel < 2 ? Ah : Al) + ch;
        const char* bB = (sel == 1 ? Bl : Bh) + ch;
        cp16(st + aDst[0], aB + aRow0);
        cp16(st + aDst[1], aB + aRow1);
#pragma unroll
        for (int j = 0; j < 4; ++j) cp16(st + bDst[j], bB + bRow[j]);
    };

    // ---- ldmatrix lane addressing (k-step advance = XOR (s<<5)) -----------
    const int lr = lane & 15;
    const int lc = lane >> 4;
    uint32_t aOff[2], bOff[4];
#pragma unroll
    for (int t = 0; t < 2; ++t)
        aOff[t] = swz(warpM * 32 + t * 16 + lr, lc);
#pragma unroll
    for (int t = 0; t < 4; ++t)
        bOff[t] = (uint32_t)A_BYTES + swz(warpN * 64 + t * 16 + lr, lc);

    float acc[2][8][4];
#pragma unroll
    for (int mt = 0; mt < 2; ++mt)
#pragma unroll
        for (int nt = 0; nt < 8; ++nt)
#pragma unroll
            for (int q = 0; q < 4; ++q) acc[mt][nt][q] = 0.0f;

    // prologue: pair 0 in flight
    load_stage(0);  load_stage(1);  CP_COMMIT();

#pragma unroll 1
    for (int g = 0; g < NGRP; ++g) {
        CP_WAIT_0();                 // pair g resident (only group in flight)
        __syncthreads();             // visible everywhere + pair g-1 compute done
        if (g + 1 < NGRP) {          // prefetch pair g+1 into pair g-1's slots
            load_stage(2 * g + 2);
            load_stage(2 * g + 3);
            CP_COMMIT();
        }
#pragma unroll
        for (int h = 0; h < 2; ++h) {            // compute the two chunks of pair g
            const int i = 2 * g + h;
            const uint32_t st = sbase + (uint32_t)(i & (STG - 1)) * STAGE_BYTES;
#pragma unroll
            for (int s = 0; s < 4; ++s) {
                const uint32_t kx = (uint32_t)s << 5;
                uint32_t a[2][4], b[4][4];
#pragma unroll
                for (int t = 0; t < 2; ++t)
                    ldsm4(a[t][0], a[t][1], a[t][2], a[t][3], st + (aOff[t] ^ kx));
#pragma unroll
                for (int t = 0; t < 4; ++t)
                    ldsm4(b[t][0], b[t][1], b[t][2], b[t][3], st + (bOff[t] ^ kx));
#pragma unroll
                for (int mt = 0; mt < 2; ++mt)
#pragma unroll
                    for (int t = 0; t < 4; ++t) {
                        mma16816(acc[mt][2*t][0], acc[mt][2*t][1], acc[mt][2*t][2], acc[mt][2*t][3],
                                 a[mt][0], a[mt][1], a[mt][2], a[mt][3], b[t][0], b[t][2]);
                        mma16816(acc[mt][2*t+1][0], acc[mt][2*t+1][1], acc[mt][2*t+1][2], acc[mt][2*t+1][3],
                                 a[mt][0], a[mt][1], a[mt][2], a[mt][3], b[t][1], b[t][3]);
                    }
            }
        }
    }

    // ---- epilogue: direct STG of register accumulators --------------------
    const int mRow = mBase + warpM * 32 + (lane >> 2);
    const int nCol = nBase + warpN * 64 + (lane & 3) * 2;
#pragma unroll
    for (int mt = 0; mt < 2; ++mt) {
        float* r0 = out + (size_t)(mRow + mt * 16)     * OUT_F + nCol;
        float* r1 = out + (size_t)(mRow + mt * 16 + 8) * OUT_F + nCol;
#pragma unroll
        for (int nt = 0; nt < 8; ++nt) {
            *(float2*)(r0 + nt * 8) = make_float2(acc[mt][nt][0], acc[mt][nt][1]);
            *(float2*)(r1 + nt * 8) = make_float2(acc[mt][nt][2], acc[mt][nt][3]);
        }
    }
}

// ---------------- launch ---------------------------------------------------
extern "C" void kernel_launch(void* const* d_in, const int* in_sizes, int n_in,
                              void* d_out, int out_size) {
    const float* x  = (const float*)d_in[0];
    const float* bw = (const float*)d_in[1];
    const float* sw = (const float*)d_in[2];
    float* out = (float*)d_out;

    cudaFuncSetAttribute(kan_gemm, cudaFuncAttributeMaxDynamicSharedMemorySize,
                         SMEM_TOTAL);

    prep_A<<<(NBAT * IN_F / 2) / 256, 256>>>(x);
    prep_B<<<(OUT_F * IN_F) / 256, 256>>>(bw, sw);
    kan_gemm<<<dim3(OUT_F / N_TILE, NBAT / M_TILE), 512, SMEM_TOTAL>>>(out);
}